// round 16
// baseline (speedup 1.0000x reference)
#include <cuda_runtime.h>
#include <cuda_bf16.h>
#include <cstdint>

#define ND 128
#define ED 64
#define HID 256
#define NMAX 100000
#define TM 64           // precompute tile
#define TME 128         // edge tile (4 quarters of 32)
#define NTHREADS 256

typedef unsigned long long ull;

__device__ __forceinline__ ull pack2(float lo, float hi) {
    ull r; asm("mov.b64 %0, {%1, %2};" : "=l"(r) : "f"(lo), "f"(hi)); return r;
}
__device__ __forceinline__ void fma2(ull &d, ull a, ull b) {
    asm("fma.rn.f32x2 %0, %1, %2, %0;" : "+l"(d) : "l"(a), "l"(b));
}
__device__ __forceinline__ ull add2(ull a, ull b) {
    ull r; asm("add.rn.f32x2 %0, %1, %2;" : "=l"(r) : "l"(a), "l"(b)); return r;
}
__device__ __forceinline__ float2 unpack2(ull v) {
    float2 f; asm("mov.b64 {%0, %1}, %2;" : "=f"(f.x), "=f"(f.y) : "l"(v)); return f;
}
__device__ __forceinline__ uint32_t smem_u32(const void* p) {
    uint32_t a;
    asm("{ .reg .u64 t; cvta.to.shared.u64 t, %1; cvt.u32.u64 %0, t; }" : "=r"(a) : "l"(p));
    return a;
}
__device__ __forceinline__ void ldsm4(uint32_t* r, uint32_t addr) {
    asm volatile("ldmatrix.sync.aligned.m8n8.x4.shared.b16 {%0,%1,%2,%3}, [%4];"
                 : "=r"(r[0]), "=r"(r[1]), "=r"(r[2]), "=r"(r[3]) : "r"(addr));
}
__device__ __forceinline__ void ldsm4t(uint32_t* r, uint32_t addr) {
    asm volatile("ldmatrix.sync.aligned.m8n8.x4.trans.shared.b16 {%0,%1,%2,%3}, [%4];"
                 : "=r"(r[0]), "=r"(r[1]), "=r"(r[2]), "=r"(r[3]) : "r"(addr));
}
__device__ __forceinline__ void mma16816(float* c, const uint32_t* a,
                                         uint32_t b0, uint32_t b1) {
    asm volatile(
        "mma.sync.aligned.m16n8k16.row.col.f32.bf16.bf16.f32 "
        "{%0,%1,%2,%3}, {%4,%5,%6,%7}, {%8,%9}, {%0,%1,%2,%3};"
        : "+f"(c[0]), "+f"(c[1]), "+f"(c[2]), "+f"(c[3])
        : "r"(a[0]), "r"(a[1]), "r"(a[2]), "r"(a[3]), "r"(b0), "r"(b1));
}
__device__ __forceinline__ uint32_t packbf(float v0, float v1) {
    uint32_t r; asm("cvt.rn.bf16x2.f32 %0, %1, %2;" : "=r"(r) : "f"(v1), "f"(v0));
    return r;
}
__device__ __forceinline__ void split_bf(float v, float& hf, float& lf) {
    __nv_bfloat16 h = __float2bfloat16(v);
    hf = __bfloat162float(h);
    lf = v - hf;
}

// device-global scratch
__device__ __align__(16) float g_Pa[(size_t)NMAX * HID];   // x@W1a + b1
__device__ __align__(16) float g_Pb[(size_t)NMAX * HID];   // x@W1b
// W2 bf16 image: 4 k-chunks, each [hi|lo][64][72]  (verified layout)
__device__ __align__(16) __nv_bfloat16 g_W2img[4][2 * 64 * 72];

// ---- edge-kernel SMEM layout (bytes) ----
// h ring: 2 slots x (hi [32][528] | lo [32][528]) = 2 x 33792
// W2 chunk buffer: [hi|lo][64][72] bf16 = 18432
// Db: fp32 [32][68] = 8704
#define HR_OFF   0
#define SLOT_SZ  33792
#define SLOT_LO  16896
#define WB_OFF   67584
#define DB_OFF   86016
#define EDGE_SMEM 94720      // -> 2 CTAs/SM

extern __shared__ float smem[];

// ===================== Prep: W2 -> bf16 hi/lo image ============================
__global__ void prep_w2(const float* __restrict__ w2) {
    int j = blockIdx.x * blockDim.x + threadIdx.x;
    if (j < HID * ED) {
        int k = j / ED, n = j % ED;
        float v = w2[(size_t)k * ED + n];
        float hf, lf; split_bf(v, hf, lf);
        int ch = k >> 6, kk = k & 63;
        g_W2img[ch][kk * 72 + n]           = __float2bfloat16(hf);
        g_W2img[ch][64 * 72 + kk * 72 + n] = __float2bfloat16(lf);
    }
}

// ============ Kernel 1: node precompute (proven R14 version) ===================
__global__ __launch_bounds__(NTHREADS, 2) void precompute_kernel(
    const float* __restrict__ x,
    const float* __restrict__ w1, const float* __restrict__ b1, int N)
{
    float* Xs = smem;              // [64][128]
    float* Bs = smem + TM * ND;    // [64][256]

    const int tid = threadIdx.x;
    const int tx  = tid & 31;
    const int ty  = tid >> 5;
    const int r0  = ty * 8;
    const int m0  = blockIdx.x * TM;

    int node[8];
    #pragma unroll
    for (int r = 0; r < 8; r++) {
        node[r] = min(m0 + r0 + r, N - 1);
        ((float4*)(Xs + (r0 + r) * ND))[tx] =
            ((const float4*)(x + (size_t)node[r] * ND))[tx];
    }

    for (int half = 0; half < 2; half++) {
        ull acc[8][4];
        if (half == 0) {
            ull bv[4];
            #pragma unroll
            for (int j = 0; j < 4; j++) {
                float2 b = ((const float2*)b1)[tx + 32 * j];
                bv[j] = pack2(b.x, b.y);
            }
            #pragma unroll
            for (int i = 0; i < 8; i++)
                #pragma unroll
                for (int j = 0; j < 4; j++) acc[i][j] = bv[j];
        } else {
            #pragma unroll
            for (int i = 0; i < 8; i++)
                #pragma unroll
                for (int j = 0; j < 4; j++) acc[i][j] = 0ull;
        }

        for (int kt = 0; kt < ND; kt += 64) {
            __syncthreads();
            const float4* wf4 = (const float4*)(w1 + (size_t)(half * ND + kt) * HID);
            #pragma unroll
            for (int it = 0; it < 16; it++) {
                int q = tid + it * NTHREADS;
                ((float4*)Bs)[q] = wf4[q];
            }
            __syncthreads();
            #pragma unroll 4
            for (int kk4 = 0; kk4 < 64; kk4 += 4) {
                float4 a4[8];
                #pragma unroll
                for (int i = 0; i < 8; i++)
                    a4[i] = *(const float4*)(Xs + (r0 + i) * ND + kt + kk4);
                #pragma unroll
                for (int kq = 0; kq < 4; kq++) {
                    const ull* Br = (const ull*)(Bs + (kk4 + kq) * HID) + tx;
                    ull b0 = Br[0], b1r = Br[32], b2r = Br[64], b3r = Br[96];
                    #pragma unroll
                    for (int i = 0; i < 8; i++) {
                        float a = (&a4[i].x)[kq];
                        ull aa = pack2(a, a);
                        fma2(acc[i][0], aa, b0);
                        fma2(acc[i][1], aa, b1r);
                        fma2(acc[i][2], aa, b2r);
                        fma2(acc[i][3], aa, b3r);
                    }
                }
            }
        }

        float* P = half ? g_Pb : g_Pa;
        #pragma unroll
        for (int i = 0; i < 8; i++) {
            float2* dst = (float2*)(P + (size_t)node[i] * HID);
            #pragma unroll
            for (int j = 0; j < 4; j++)
                dst[tx + 32 * j] = unpack2(acc[i][j]);
        }
    }
}

// ====== Kernel 2: edge — interleaved GEMM1(fma) / GEMM2(HMMA) pipeline =========
__global__ __launch_bounds__(NTHREADS, 2) void edge_kernel(
    const int* __restrict__ ei32,
    const float* __restrict__ edge_attr,
    const float* __restrict__ w1,       // rows [256,320) = W1c (LDG broadcast)
    const float* __restrict__ b2,
    const float* __restrict__ ln_w, const float* __restrict__ ln_b,
    float* __restrict__ out, int E, int N)
{
    unsigned char* sm = (unsigned char*)smem;
    const uint32_t sb = smem_u32(sm);

    const int tid  = threadIdx.x;
    const int tx   = tid & 31;
    const int lane = tx;
    const int w    = tid >> 5;       // 0..7
    const int mg   = w & 1;          // mma row group (16 rows of 32)
    const int ng   = w >> 1;         // mma col group (16 cols of 64)
    const int e0   = blockIdx.x * TME;

    unsigned oddbits = 0;
    #pragma unroll
    for (int k = 0; k < 16; k++) oddbits |= (unsigned)ei32[2 * k + 1];
    const int step = (oddbits == 0) ? 2 : 1;

    const float* w1c = w1 + (size_t)(2 * ND) * HID;
    float2 b2v = ((const float2*)b2)[tx];
    float2 lwv = ((const float2*)ln_w)[tx];
    float2 lbv = ((const float2*)ln_b)[tx];

    for (int q = 0; q < 5; q++) {
        const bool doG1  = (q < 4);
        const bool doMMA = (q > 0);

        // ---- gather + acc init for quarter q (rows 4w..4w+3 of quarter) ----
        ull acc[4][4];
        int erow[4];
        if (doG1) {
            #pragma unroll
            for (int i = 0; i < 4; i++) {
                int e = min(e0 + q * 32 + 4 * w + i, E - 1);
                erow[i] = e;
                int ss = ei32[(size_t)step * e];
                int ds = ei32[(size_t)step * (E + e)];
                ss = min(max(ss, 0), N - 1);
                ds = min(max(ds, 0), N - 1);
                const ulonglong2* pa = (const ulonglong2*)(g_Pa + (size_t)ds * HID);
                const ulonglong2* pb = (const ulonglong2*)(g_Pb + (size_t)ss * HID);
                ulonglong2 a0 = pa[tx],      b0 = pb[tx];
                ulonglong2 a1 = pa[tx + 32], b1v = pb[tx + 32];
                acc[i][0] = add2(a0.x, b0.x);
                acc[i][1] = add2(a0.y, b0.y);
                acc[i][2] = add2(a1.x, b1v.x);
                acc[i][3] = add2(a1.y, b1v.y);
            }
        }

        float c2[2][4];
        #pragma unroll
        for (int j = 0; j < 2; j++)
            #pragma unroll
            for (int p = 0; p < 4; p++) c2[j][p] = 0.f;

        const uint32_t slotA = sb + HR_OFF + ((q - 1) & 1) * SLOT_SZ;

        // ---- 4 chunks: mma(q-1, ch) interleaved with GEMM1(q) piece ch ----
        for (int ch = 0; ch < 4; ch++) {
            if (doMMA) {
                __syncthreads();
                {   // stage W2 chunk ch (1152 float4)
                    const float4* src = (const float4*)g_W2img[ch];
                    float4* dst = (float4*)(sm + WB_OFF);
                    #pragma unroll
                    for (int p = 0; p < 5; p++) {
                        int idx = tid + p * NTHREADS;
                        if (idx < 1152) dst[idx] = src[idx];
                    }
                }
                __syncthreads();
                #pragma unroll
                for (int k16 = 0; k16 < 4; k16++) {
                    uint32_t aAddr = slotA + (16 * mg + (lane & 15)) * 528
                                   + (64 * ch + 16 * k16) * 2 + (lane >> 4) * 16;
                    uint32_t ah[4], al[4];
                    ldsm4(ah, aAddr);
                    ldsm4(al, aAddr + SLOT_LO);
                    uint32_t bAddr = sb + WB_OFF + (k16 * 16 + (lane & 15)) * 144
                                   + (16 * ng) * 2 + (lane >> 4) * 16;
                    uint32_t bh[4], bl[4];
                    ldsm4t(bh, bAddr);
                    ldsm4t(bl, bAddr + 9216);
                    mma16816(c2[0], ah, bh[0], bh[1]);
                    mma16816(c2[0], al, bh[0], bh[1]);
                    mma16816(c2[0], ah, bl[0], bl[1]);
                    mma16816(c2[1], ah, bh[2], bh[3]);
                    mma16816(c2[1], al, bh[2], bh[3]);
                    mma16816(c2[1], ah, bl[2], bl[3]);
                }
            }
            if (doG1) {
                // GEMM1 piece: kk4 in [16ch, 16ch+16)
                #pragma unroll
                for (int kk4 = 16 * ch; kk4 < 16 * ch + 16; kk4 += 4) {
                    float4 a4[4];
                    #pragma unroll
                    for (int i = 0; i < 4; i++)
                        a4[i] = __ldg((const float4*)(edge_attr + (size_t)erow[i] * ED) + (kk4 >> 2));
                    #pragma unroll
                    for (int kq = 0; kq < 4; kq++) {
                        const ulonglong2* Br = (const ulonglong2*)(w1c + (kk4 + kq) * HID);
                        ulonglong2 bA = Br[tx];
                        ulonglong2 bB = Br[tx + 32];
                        #pragma unroll
                        for (int i = 0; i < 4; i++) {
                            float a = (&a4[i].x)[kq];
                            ull aa = pack2(a, a);
                            fma2(acc[i][0], aa, bA.x);
                            fma2(acc[i][1], aa, bA.y);
                            fma2(acc[i][2], aa, bB.x);
                            fma2(acc[i][3], aa, bB.y);
                        }
                    }
                }
            }
        }

        // ---- h(q) = relu(acc) -> slot q&1 (bf16 hi/lo) ----
        if (doG1) {
            unsigned slot = HR_OFF + (q & 1) * SLOT_SZ;
            #pragma unroll
            for (int i = 0; i < 4; i++) {
                unsigned rbase = slot + (4 * w + i) * 528;
                #pragma unroll
                for (int j = 0; j < 4; j++) {
                    float2 v = unpack2(acc[i][j]);
                    v.x = fmaxf(v.x, 0.f);
                    v.y = fmaxf(v.y, 0.f);
                    float h0, l0, h1, l1;
                    split_bf(v.x, h0, l0);
                    split_bf(v.y, h1, l1);
                    unsigned cb = (j < 2) ? (8 * tx + 4 * j) : (256 + 8 * tx + 4 * (j - 2));
                    *(uint32_t*)(sm + rbase + cb)           = packbf(h0, h1);
                    *(uint32_t*)(sm + rbase + SLOT_LO + cb) = packbf(l0, l1);
                }
            }
        }

        // ---- delta stage + LN for quarter q-1 ----
        if (doMMA) {
            __syncthreads();   // all mma for q-1 done; Db free from prior LN
            {
                float* Db = (float*)(sm + DB_OFF);
                const int rlo = 16 * mg + (lane >> 2);
                const int rhi = rlo + 8;
                const int cq2 = 2 * (lane & 3);
                #pragma unroll
                for (int j = 0; j < 2; j++) {
                    int col = 16 * ng + 8 * j + cq2;
                    *(float2*)(Db + rlo * 68 + col) = make_float2(c2[j][0], c2[j][1]);
                    *(float2*)(Db + rhi * 68 + col) = make_float2(c2[j][2], c2[j][3]);
                }
            }
            __syncthreads();
            {
                const float* Db = (const float*)(sm + DB_OFF);
                const int qq = q - 1;
                #pragma unroll
                for (int i = 0; i < 4; i++) {
                    int r = 4 * w + i;
                    int e = e0 + qq * 32 + r;
                    int ec = min(e, E - 1);
                    float2 d  = *(const float2*)(Db + r * 68 + 2 * tx);
                    float2 ar = ((const float2*)(edge_attr + (size_t)ec * ED))[tx];
                    float v0 = ar.x + d.x + b2v.x;
                    float v1 = ar.y + d.y + b2v.y;
                    float s = v0 + v1;
                    float qs = v0 * v0 + v1 * v1;
                    #pragma unroll
                    for (int off = 16; off > 0; off >>= 1) {
                        s  += __shfl_xor_sync(0xffffffffu, s, off);
                        qs += __shfl_xor_sync(0xffffffffu, qs, off);
                    }
                    float mean = s * 0.015625f;
                    float var  = qs * 0.015625f - mean * mean;
                    float inv  = rsqrtf(var + 1e-5f);
                    if (e < E) {
                        float2 o;
                        o.x = (v0 - mean) * inv * lwv.x + lbv.x;
                        o.y = (v1 - mean) * inv * lwv.y + lbv.y;
                        ((float2*)(out + (size_t)e * ED))[tx] = o;
                    }
                }
            }
        }
    }
}

extern "C" void kernel_launch(void* const* d_in, const int* in_sizes, int n_in,
                              void* d_out, int out_size) {
    const float* x   = (const float*)d_in[0];
    const int*   ei  = (const int*)d_in[1];
    const float* ea  = (const float*)d_in[2];
    const float* w1  = (const float*)d_in[3];
    const float* b1  = (const float*)d_in[4];
    const float* w2  = (const float*)d_in[5];
    const float* b2  = (const float*)d_in[6];
    const float* lnw = (const float*)d_in[7];
    const float* lnb = (const float*)d_in[8];
    float* out = (float*)d_out;

    int E = in_sizes[1] / 2;
    int N = in_sizes[0] / ND;

    static int init_done = 0;
    int smem_pre = (TM * ND + TM * HID) * (int)sizeof(float);   // 98304
    if (!init_done) {
        cudaFuncSetAttribute(precompute_kernel,
                             cudaFuncAttributeMaxDynamicSharedMemorySize, smem_pre);
        cudaFuncSetAttribute(edge_kernel,
                             cudaFuncAttributeMaxDynamicSharedMemorySize, EDGE_SMEM);
        init_done = 1;
    }

    prep_w2<<<(HID * ED + 255) / 256, 256>>>(w2);

    int pgrid = (N + TM - 1) / TM;
    precompute_kernel<<<pgrid, NTHREADS, smem_pre>>>(x, w1, b1, N);

    int egrid = (E + TME - 1) / TME;
    edge_kernel<<<egrid, NTHREADS, EDGE_SMEM>>>(
        ei, ea, w1, b2, lnw, lnb, out, E, N);
}

// round 17
// speedup vs baseline: 1.2507x; 1.2507x over previous
#include <cuda_runtime.h>
#include <cuda_bf16.h>
#include <cstdint>

#define ND 128
#define ED 64
#define HID 256
#define NMAX 100000
#define TM 64
#define NTHREADS 256

typedef unsigned long long ull;

__device__ __forceinline__ ull pack2(float lo, float hi) {
    ull r; asm("mov.b64 %0, {%1, %2};" : "=l"(r) : "f"(lo), "f"(hi)); return r;
}
__device__ __forceinline__ void fma2(ull &d, ull a, ull b) {
    asm("fma.rn.f32x2 %0, %1, %2, %0;" : "+l"(d) : "l"(a), "l"(b));
}
__device__ __forceinline__ ull add2(ull a, ull b) {
    ull r; asm("add.rn.f32x2 %0, %1, %2;" : "=l"(r) : "l"(a), "l"(b)); return r;
}
__device__ __forceinline__ float2 unpack2(ull v) {
    float2 f; asm("mov.b64 {%0, %1}, %2;" : "=f"(f.x), "=f"(f.y) : "l"(v)); return f;
}
__device__ __forceinline__ uint32_t tf32cvt(float f) {
    uint32_t r; asm("cvt.rna.tf32.f32 %0, %1;" : "=r"(r) : "f"(f)); return r;
}
__device__ __forceinline__ void mma_tf32(float* c, uint32_t a0, uint32_t a1,
                                         uint32_t a2, uint32_t a3,
                                         uint32_t b0, uint32_t b1) {
    asm volatile(
        "mma.sync.aligned.m16n8k8.row.col.f32.tf32.tf32.f32 "
        "{%0,%1,%2,%3}, {%4,%5,%6,%7}, {%8,%9}, {%0,%1,%2,%3};"
        : "+f"(c[0]), "+f"(c[1]), "+f"(c[2]), "+f"(c[3])
        : "r"(a0), "r"(a1), "r"(a2), "r"(a3), "r"(b0), "r"(b1));
}

// device-global scratch
__device__ __align__(16) float g_Pa[(size_t)NMAX * HID];   // x@W1a + b1
__device__ __align__(16) float g_Pb[(size_t)NMAX * HID];   // x@W1b
// W2 tf32 fragments: index = ((S*8 + n8)*32 + lane)*2 + r
//   value = tf32(w2[(8S + (lane&3) + 4r)*64 + 8*n8 + (lane>>2)])
__device__ __align__(16) uint32_t g_W2frag[32 * 8 * 32 * 2];

// ---- edge-kernel SMEM (floats): Es [64][64] | Hs [64][268] tf32 | Db [64][68]
#define HS_F   4096
#define DB_F   (4096 + 64 * 268)      // 21248
#define EDGE_SMEM ((4096 + 64 * 268 + 64 * 68) * 4)   // 102400 B -> 2 CTAs/SM

extern __shared__ float smem[];

// ===================== Prep: W2 -> tf32 fragment order =========================
__global__ void prep_w2(const float* __restrict__ w2) {
    int i = blockIdx.x * blockDim.x + threadIdx.x;   // 16384
    if (i < 32 * 8 * 32 * 2) {
        int r    = i & 1;
        int lane = (i >> 1) & 31;
        int n8   = (i >> 6) & 7;
        int S    = i >> 9;
        int t = lane & 3, g = lane >> 2;
        int k = 8 * S + t + 4 * r;
        int n = 8 * n8 + g;
        g_W2frag[i] = tf32cvt(w2[(size_t)k * ED + n]);
    }
}

// ============ Kernel 1: node precompute (proven R14 version) ===================
__global__ __launch_bounds__(NTHREADS, 2) void precompute_kernel(
    const float* __restrict__ x,
    const float* __restrict__ w1, const float* __restrict__ b1, int N)
{
    float* Xs = smem;              // [64][128]
    float* Bs = smem + TM * ND;    // [64][256]

    const int tid = threadIdx.x;
    const int tx  = tid & 31;
    const int ty  = tid >> 5;
    const int r0  = ty * 8;
    const int m0  = blockIdx.x * TM;

    int node[8];
    #pragma unroll
    for (int r = 0; r < 8; r++) {
        node[r] = min(m0 + r0 + r, N - 1);
        ((float4*)(Xs + (r0 + r) * ND))[tx] =
            ((const float4*)(x + (size_t)node[r] * ND))[tx];
    }

    for (int half = 0; half < 2; half++) {
        ull acc[8][4];
        if (half == 0) {
            ull bv[4];
            #pragma unroll
            for (int j = 0; j < 4; j++) {
                float2 b = ((const float2*)b1)[tx + 32 * j];
                bv[j] = pack2(b.x, b.y);
            }
            #pragma unroll
            for (int i = 0; i < 8; i++)
                #pragma unroll
                for (int j = 0; j < 4; j++) acc[i][j] = bv[j];
        } else {
            #pragma unroll
            for (int i = 0; i < 8; i++)
                #pragma unroll
                for (int j = 0; j < 4; j++) acc[i][j] = 0ull;
        }

        for (int kt = 0; kt < ND; kt += 64) {
            __syncthreads();
            const float4* wf4 = (const float4*)(w1 + (size_t)(half * ND + kt) * HID);
            #pragma unroll
            for (int it = 0; it < 16; it++) {
                int q = tid + it * NTHREADS;
                ((float4*)Bs)[q] = wf4[q];
            }
            __syncthreads();
            #pragma unroll 4
            for (int kk4 = 0; kk4 < 64; kk4 += 4) {
                float4 a4[8];
                #pragma unroll
                for (int i = 0; i < 8; i++)
                    a4[i] = *(const float4*)(Xs + (r0 + i) * ND + kt + kk4);
                #pragma unroll
                for (int kq = 0; kq < 4; kq++) {
                    const ull* Br = (const ull*)(Bs + (kk4 + kq) * HID) + tx;
                    ull b0 = Br[0], b1r = Br[32], b2r = Br[64], b3r = Br[96];
                    #pragma unroll
                    for (int i = 0; i < 8; i++) {
                        float a = (&a4[i].x)[kq];
                        ull aa = pack2(a, a);
                        fma2(acc[i][0], aa, b0);
                        fma2(acc[i][1], aa, b1r);
                        fma2(acc[i][2], aa, b2r);
                        fma2(acc[i][3], aa, b3r);
                    }
                }
            }
        }

        float* P = half ? g_Pb : g_Pa;
        #pragma unroll
        for (int i = 0; i < 8; i++) {
            float2* dst = (float2*)(P + (size_t)node[i] * HID);
            #pragma unroll
            for (int j = 0; j < 4; j++)
                dst[tx + 32 * j] = unpack2(acc[i][j]);
        }
    }
}

// ========== Kernel 2: edge — GEMM1 on FFMA2, GEMM2 on tf32 MMA =================
__global__ __launch_bounds__(NTHREADS, 2) void edge_kernel(
    const int* __restrict__ ei32,
    const float* __restrict__ edge_attr,
    const float* __restrict__ w1,       // rows [256,320) = W1c (LDG)
    const float* __restrict__ b2,
    const float* __restrict__ ln_w, const float* __restrict__ ln_b,
    float* __restrict__ out, int E, int N)
{
    float* Es = smem;
    float* Hs = smem + HS_F;
    float* Db = smem + DB_F;

    const int tid = threadIdx.x;
    const int tx  = tid & 31;
    const int ty  = tid >> 5;          // warp 0..7
    const int r0  = ty * 8;
    const int e0  = blockIdx.x * TM;

    // int64/int32 detection
    unsigned oddbits = 0;
    #pragma unroll
    for (int k = 0; k < 16; k++) oddbits |= (unsigned)ei32[2 * k + 1];
    const int step = (oddbits == 0) ? 2 : 1;

    // ---- gather: ea -> Es (own rows); acc = Pa[dst] + Pb[src] (LDG.128) ----
    ull acc[8][4];
    #pragma unroll
    for (int r = 0; r < 8; r++) {
        int e = min(e0 + r0 + r, E - 1);
        int ss = ei32[(size_t)step * e];
        int ds = ei32[(size_t)step * (E + e)];
        ss = min(max(ss, 0), N - 1);
        ds = min(max(ds, 0), N - 1);
        if (tx < 16)
            ((float4*)(Es + (r0 + r) * ED))[tx] =
                ((const float4*)(edge_attr + (size_t)e * ED))[tx];
        const ulonglong2* pa = (const ulonglong2*)(g_Pa + (size_t)ds * HID);
        const ulonglong2* pb = (const ulonglong2*)(g_Pb + (size_t)ss * HID);
        ulonglong2 a0 = pa[tx],      b0 = pb[tx];
        ulonglong2 a1 = pa[tx + 32], b1v = pb[tx + 32];
        acc[r][0] = add2(a0.x, b0.x);    // cols 4tx..+1
        acc[r][1] = add2(a0.y, b0.y);    // cols 4tx+2..+3
        acc[r][2] = add2(a1.x, b1v.x);   // cols 128+4tx..+1
        acc[r][3] = add2(a1.y, b1v.y);
    }
    __syncwarp();

    // ---- GEMM1 remainder: acc += ea @ W1c (K=64), B via LDG.128 ----
    const float* w1c = w1 + (size_t)(2 * ND) * HID;
    #pragma unroll 4
    for (int kk4 = 0; kk4 < ED; kk4 += 4) {
        float4 a4[8];
        #pragma unroll
        for (int i = 0; i < 8; i++)
            a4[i] = *(const float4*)(Es + (r0 + i) * ED + kk4);
        #pragma unroll
        for (int kq = 0; kq < 4; kq++) {
            const ulonglong2* Br = (const ulonglong2*)(w1c + (kk4 + kq) * HID);
            ulonglong2 bA = Br[tx];
            ulonglong2 bB = Br[tx + 32];
            #pragma unroll
            for (int i = 0; i < 8; i++) {
                float a = (&a4[i].x)[kq];
                ull aa = pack2(a, a);
                fma2(acc[i][0], aa, bA.x);
                fma2(acc[i][1], aa, bA.y);
                fma2(acc[i][2], aa, bB.x);
                fma2(acc[i][3], aa, bB.y);
            }
        }
    }

    // ---- h = relu(acc) -> tf32 into Hs [64][268] (2x STS.128 per row) ----
    #pragma unroll
    for (int i = 0; i < 8; i++) {
        uint32_t* hr = (uint32_t*)(Hs + (r0 + i) * 268);
        float2 v0 = unpack2(acc[i][0]);
        float2 v1 = unpack2(acc[i][1]);
        float2 v2 = unpack2(acc[i][2]);
        float2 v3 = unpack2(acc[i][3]);
        uint4 p0, p1;
        p0.x = tf32cvt(fmaxf(v0.x, 0.f)); p0.y = tf32cvt(fmaxf(v0.y, 0.f));
        p0.z = tf32cvt(fmaxf(v1.x, 0.f)); p0.w = tf32cvt(fmaxf(v1.y, 0.f));
        p1.x = tf32cvt(fmaxf(v2.x, 0.f)); p1.y = tf32cvt(fmaxf(v2.y, 0.f));
        p1.z = tf32cvt(fmaxf(v3.x, 0.f)); p1.w = tf32cvt(fmaxf(v3.y, 0.f));
        *(uint4*)(hr + 4 * tx)       = p0;   // cols 4tx..4tx+3
        *(uint4*)(hr + 128 + 4 * tx) = p1;   // cols 128+4tx..+3
    }
    __syncthreads();   // h visible to all warps

    // ---- GEMM2: delta = h @ W2 (tf32 single pass, barrier-free) ----
    // warp (mg, ng): rows [16mg,16mg+16), cols [32ng,32ng+32)
    const int mg = ty & 3, ng = ty >> 2;
    const int g  = tx >> 2, t = tx & 3;
    float c2[4][4];
    #pragma unroll
    for (int j = 0; j < 4; j++)
        #pragma unroll
        for (int p = 0; p < 4; p++) c2[j][p] = 0.f;

    const uint32_t* Ha = (const uint32_t*)Hs;
    const int rowA = (16 * mg + g) * 268;
    #pragma unroll 4
    for (int S = 0; S < 32; S++) {
        uint32_t a0 = Ha[rowA + 8 * S + t];
        uint32_t a1 = Ha[rowA + 8 * 268 + 8 * S + t];
        uint32_t a2 = Ha[rowA + 8 * S + t + 4];
        uint32_t a3 = Ha[rowA + 8 * 268 + 8 * S + t + 4];
        #pragma unroll
        for (int j = 0; j < 4; j++) {
            uint2 b = *((const uint2*)g_W2frag + (size_t)(S * 8 + 4 * ng + j) * 32 + tx);
            mma_tf32(c2[j], a0, a1, a2, a3, b.x, b.y);
        }
    }

    // ---- stage delta into Db [64][68] ----
    {
        const int rlo = 16 * mg + g;
        const int rhi = rlo + 8;
        const int cq2 = 2 * t;
        #pragma unroll
        for (int j = 0; j < 4; j++) {
            int col = 32 * ng + 8 * j + cq2;
            *(float2*)(Db + rlo * 68 + col) = make_float2(c2[j][0], c2[j][1]);
            *(float2*)(Db + rhi * 68 + col) = make_float2(c2[j][2], c2[j][3]);
        }
    }
    __syncthreads();

    // ---- Epilogue: residual + LayerNorm(64) + affine (cols {2tx,2tx+1}) ----
    float2 b2v = ((const float2*)b2)[tx];
    float2 lwv = ((const float2*)ln_w)[tx];
    float2 lbv = ((const float2*)ln_b)[tx];

    #pragma unroll
    for (int i = 0; i < 8; i++) {
        int r = r0 + i;
        float2 d  = *(const float2*)(Db + r * 68 + 2 * tx);
        float2 ar = ((const float2*)(Es + r * ED))[tx];
        float v0 = ar.x + d.x + b2v.x;
        float v1 = ar.y + d.y + b2v.y;
        float s = v0 + v1;
        float q = v0 * v0 + v1 * v1;
        #pragma unroll
        for (int off = 16; off > 0; off >>= 1) {
            s += __shfl_xor_sync(0xffffffffu, s, off);
            q += __shfl_xor_sync(0xffffffffu, q, off);
        }
        float mean = s * 0.015625f;
        float var  = q * 0.015625f - mean * mean;
        float inv  = rsqrtf(var + 1e-5f);
        int e = e0 + r;
        if (e < E) {
            float2 o;
            o.x = (v0 - mean) * inv * lwv.x + lbv.x;
            o.y = (v1 - mean) * inv * lwv.y + lbv.y;
            ((float2*)(out + (size_t)e * ED))[tx] = o;
        }
    }
}

extern "C" void kernel_launch(void* const* d_in, const int* in_sizes, int n_in,
                              void* d_out, int out_size) {
    const float* x   = (const float*)d_in[0];
    const int*   ei  = (const int*)d_in[1];
    const float* ea  = (const float*)d_in[2];
    const float* w1  = (const float*)d_in[3];
    const float* b1  = (const float*)d_in[4];
    const float* w2  = (const float*)d_in[5];
    const float* b2  = (const float*)d_in[6];
    const float* lnw = (const float*)d_in[7];
    const float* lnb = (const float*)d_in[8];
    float* out = (float*)d_out;

    int E = in_sizes[1] / 2;
    int N = in_sizes[0] / ND;

    static int init_done = 0;
    int smem_pre = (TM * ND + TM * HID) * (int)sizeof(float);   // 98304
    if (!init_done) {
        cudaFuncSetAttribute(precompute_kernel,
                             cudaFuncAttributeMaxDynamicSharedMemorySize, smem_pre);
        cudaFuncSetAttribute(edge_kernel,
                             cudaFuncAttributeMaxDynamicSharedMemorySize, EDGE_SMEM);
        init_done = 1;
    }

    prep_w2<<<64, 256>>>(w2);

    int pgrid = (N + TM - 1) / TM;
    precompute_kernel<<<pgrid, NTHREADS, smem_pre>>>(x, w1, b1, N);

    int egrid = (E + TM - 1) / TM;
    edge_kernel<<<egrid, NTHREADS, EDGE_SMEM>>>(
        ei, ea, w1, b2, lnw, lnb, out, E, N);
}